// round 17
// baseline (speedup 1.0000x reference)
#include <cuda_runtime.h>
#include <cuda_bf16.h>
#include <cstdint>

// out[b,n,h] = (q_b @ Vw^T)[n,h] * softmax_m(q_b @ Wc @ k_b^T)[n,m=h]
// Wc = 0.125*Kw^T Qw (prep). Stage A (f32 SIMT): KW = key_b @ Wc.
// Main GEMM: D[224x128] = q_pad @ [KW | Vw]^T via mma.sync m16n8k16 bf16x3.
// MMA work unit = (m-tile-pair, col-half): B frags shared across 2 m-tiles
// (LDS/MMA 2.25 -> 1.5). Split softmax: per-half (max,expsum) exchanged via smem.
// B=4096, N=200, E=H=M=64, f32 I/O. Plain sm_100 target.

#define TB 256
#define AST 72   // bf16 row stride = 144 B -> conflict-free fragment LDS
#define BST 72

// smem byte offsets
#define OFF_A_HI 0
#define OFF_A_LO 32256                  // A: 224 rows x 144 B
#define OFF_B_HI 64512                  // B: 128 rows x 144 B
#define OFF_B_LO 82944
#define OFF_EXCH 101376                 // 7 pairs x 32 rows x 2 halves x 2 f32
#define SMEM_TOTAL 104960
// f32 scratch aliases the A region (dead before A is written)
#define OFF_KEYF 0                      // Ks  [64][68] f32 = 17408 B
#define OFF_WCF  17408                  // Wcs [64][64] f32 = 16384 B

__device__ __align__(16) float g_Wc[64 * 64];

// ---- packed f32x2 helpers (stage A) ----
__device__ __forceinline__ unsigned long long pk2(float x, float y) {
    unsigned long long r; asm("mov.b64 %0, {%1, %2};" : "=l"(r) : "f"(x), "f"(y)); return r;
}
__device__ __forceinline__ void fma2(unsigned long long& d, unsigned long long a, unsigned long long b) {
    asm("fma.rn.f32x2 %0, %1, %2, %0;" : "+l"(d) : "l"(a), "l"(b));
}
__device__ __forceinline__ float2 up2(unsigned long long v) {
    float lo, hi; asm("mov.b64 {%0, %1}, %2;" : "=f"(lo), "=f"(hi) : "l"(v));
    return make_float2(lo, hi);
}

// bf16 mma, f32 accum (HMMA)
__device__ __forceinline__ void mma16816(float* c, uint32_t a0, uint32_t a1,
                                         uint32_t a2, uint32_t a3,
                                         uint32_t b0, uint32_t b1) {
    asm volatile(
        "mma.sync.aligned.m16n8k16.row.col.f32.bf16.bf16.f32 "
        "{%0,%1,%2,%3}, {%4,%5,%6,%7}, {%8,%9}, {%0,%1,%2,%3};"
        : "+f"(c[0]), "+f"(c[1]), "+f"(c[2]), "+f"(c[3])
        : "r"(a0), "r"(a1), "r"(a2), "r"(a3), "r"(b0), "r"(b1));
}

// split 8 f32 -> bf16 hi + bf16 residual lo, 16B packed stores
__device__ __forceinline__ void split8(char* hip, char* lop, const float* v) {
    uint32_t hs[8], ls[8];
#pragma unroll
    for (int j = 0; j < 8; j++) {
        __nv_bfloat16 h = __float2bfloat16_rn(v[j]);
        __nv_bfloat16 l = __float2bfloat16_rn(v[j] - __bfloat162float(h));
        hs[j] = (uint32_t)__bfloat16_as_ushort(h);
        ls[j] = (uint32_t)__bfloat16_as_ushort(l);
    }
    *reinterpret_cast<uint4*>(hip) = make_uint4(hs[0] | (hs[1] << 16), hs[2] | (hs[3] << 16),
                                                hs[4] | (hs[5] << 16), hs[6] | (hs[7] << 16));
    *reinterpret_cast<uint4*>(lop) = make_uint4(ls[0] | (ls[1] << 16), ls[2] | (ls[3] << 16),
                                                ls[4] | (ls[5] << 16), ls[6] | (ls[7] << 16));
}

__global__ void prep_kernel(const float* __restrict__ Qw, const float* __restrict__ Kw) {
    int t = blockIdx.x * blockDim.x + threadIdx.x;  // 0..4095
    int r = t >> 6, c = t & 63;
    float s = 0.f;
#pragma unroll
    for (int h = 0; h < 64; h++) s += Kw[h * 64 + r] * Qw[h * 64 + c];
    g_Wc[t] = s * 0.125f;
}

__global__ __launch_bounds__(256, 2) void fused_kernel(const float* __restrict__ q,
                                                       const float* __restrict__ key,
                                                       const float* __restrict__ Vw,
                                                       float* __restrict__ out) {
    extern __shared__ char smem[];
    const int tid = threadIdx.x;
    const int wid = tid >> 5;
    const int lane = tid & 31;
    const int b = blockIdx.x;
    const float* kb = key + (size_t)b * 4096;
    const float* qb = q + (size_t)b * 12800;
    float* outb = out + (size_t)b * 12800;
    float* exch = reinterpret_cast<float*>(smem + OFF_EXCH);

    // phase 1: key -> Ks f32 [64][68], Wc -> Wcs f32 [64][64] (alias A region);
    //          Vw -> B rows 64..127 (bf16 hi/lo)
    float* Ks = reinterpret_cast<float*>(smem + OFF_KEYF);
    float* Wcs = reinterpret_cast<float*>(smem + OFF_WCF);
    for (int i = tid; i < 1024; i += TB) {
        int m = i >> 4, e4 = i & 15;
        *reinterpret_cast<float4*>(&Ks[m * 68 + e4 * 4]) =
            reinterpret_cast<const float4*>(kb)[i];
    }
    for (int i = tid; i < 1024; i += TB)
        reinterpret_cast<float4*>(Wcs)[i] = reinterpret_cast<const float4*>(g_Wc)[i];
    for (int i = tid; i < 512; i += TB) {
        int h = i >> 3, c8 = (i & 7) * 8;
        float v[8];
        *reinterpret_cast<float4*>(v) = *reinterpret_cast<const float4*>(Vw + h * 64 + c8);
        *reinterpret_cast<float4*>(v + 4) = *reinterpret_cast<const float4*>(Vw + h * 64 + c8 + 4);
        uint32_t off = (uint32_t)(64 + h) * (BST * 2) + c8 * 2;
        split8(smem + OFF_B_HI + off, smem + OFF_B_LO + off, v);
    }
    __syncthreads();

    // stage A (f32): KW[m][e] = sum_e' Ks[m][e'] * Wcs[e'][e], 4x4 per thread
    const int txA = tid & 15, tyA = tid >> 4;
    const int m0A = tyA * 4, e0A = txA * 4;
    float accf[4][4];
    {
        unsigned long long acc[4][2] = {};
#pragma unroll
        for (int ep = 0; ep < 64; ep += 4) {
            float4 a[4];
#pragma unroll
            for (int ii = 0; ii < 4; ii++)
                a[ii] = *reinterpret_cast<const float4*>(&Ks[(m0A + ii) * 68 + ep]);
#pragma unroll
            for (int kk = 0; kk < 4; kk++) {
                ulonglong2 w = *reinterpret_cast<const ulonglong2*>(&Wcs[(ep + kk) * 64 + e0A]);
#pragma unroll
                for (int ii = 0; ii < 4; ii++) {
                    float av = (kk == 0) ? a[ii].x : (kk == 1) ? a[ii].y
                             : (kk == 2) ? a[ii].z : a[ii].w;
                    unsigned long long a2 = pk2(av, av);
                    fma2(acc[ii][0], a2, w.x);
                    fma2(acc[ii][1], a2, w.y);
                }
            }
        }
#pragma unroll
        for (int ii = 0; ii < 4; ii++) {
            float2 p0 = up2(acc[ii][0]), p1 = up2(acc[ii][1]);
            accf[ii][0] = p0.x; accf[ii][1] = p0.y; accf[ii][2] = p1.x; accf[ii][3] = p1.y;
        }
    }
    // KW -> B rows 0..63 (hi/lo)
#pragma unroll
    for (int ii = 0; ii < 4; ii++) {
        uint32_t h2[2], l2[2];
#pragma unroll
        for (int jj = 0; jj < 2; jj++) {
            __nv_bfloat16 ha = __float2bfloat16_rn(accf[ii][2 * jj]);
            __nv_bfloat16 hb = __float2bfloat16_rn(accf[ii][2 * jj + 1]);
            __nv_bfloat16 la = __float2bfloat16_rn(accf[ii][2 * jj] - __bfloat162float(ha));
            __nv_bfloat16 lb = __float2bfloat16_rn(accf[ii][2 * jj + 1] - __bfloat162float(hb));
            h2[jj] = (uint32_t)__bfloat16_as_ushort(ha) | ((uint32_t)__bfloat16_as_ushort(hb) << 16);
            l2[jj] = (uint32_t)__bfloat16_as_ushort(la) | ((uint32_t)__bfloat16_as_ushort(lb) << 16);
        }
        uint32_t off = (uint32_t)(m0A + ii) * (BST * 2) + e0A * 2;
        *reinterpret_cast<uint2*>(smem + OFF_B_HI + off) = make_uint2(h2[0], h2[1]);
        *reinterpret_cast<uint2*>(smem + OFF_B_LO + off) = make_uint2(l2[0], l2[1]);
    }
    __syncthreads();  // scratch reads done; A region reusable

    // q -> A rows 0..199 (hi/lo), zero-pad rows 200..223
    for (int i = tid; i < 1600; i += TB) {
        int n = i >> 3, c8 = (i & 7) * 8;
        float v[8];
        *reinterpret_cast<float4*>(v) = *reinterpret_cast<const float4*>(qb + n * 64 + c8);
        *reinterpret_cast<float4*>(v + 4) = *reinterpret_cast<const float4*>(qb + n * 64 + c8 + 4);
        uint32_t off = (uint32_t)n * (AST * 2) + c8 * 2;
        split8(smem + OFF_A_HI + off, smem + OFF_A_LO + off, v);
    }
    for (int i = tid; i < 432; i += TB) {
        uint4 z = make_uint4(0, 0, 0, 0);
        if (i < 216)
            *reinterpret_cast<uint4*>(smem + OFF_A_HI + 200 * (AST * 2) + i * 16) = z;
        else
            *reinterpret_cast<uint4*>(smem + OFF_A_LO + 200 * (AST * 2) + (i - 216) * 16) = z;
    }
    __syncthreads();

    // main GEMM: unit = (m-tile-pair p, col-half j); 7 pairs x 2 halves = 14 units,
    // 2 fixed rounds over 8 warps. Per unit: 2 m16-tiles x 8 n8-tiles (4 logit + 4 V).
    const int g = lane >> 2;
    const int c = lane & 3;
#pragma unroll 1
    for (int round = 0; round < 2; round++) {
        const int u = round * 8 + wid;
        const bool act = (u < 14);
        const int p = u >> 1;
        const int j = u & 1;
        float acc[2][8][4];
        float mxr[2][2], sr[2][2];
        if (act) {
#pragma unroll
            for (int tt = 0; tt < 2; tt++)
#pragma unroll
                for (int nt = 0; nt < 8; nt++) {
                    acc[tt][nt][0] = 0.f; acc[tt][nt][1] = 0.f;
                    acc[tt][nt][2] = 0.f; acc[tt][nt][3] = 0.f;
                }
            uint32_t arow[2][2];
#pragma unroll
            for (int tt = 0; tt < 2; tt++) {
                arow[tt][0] = (uint32_t)(32 * p + 16 * tt + g) * (AST * 2);
                arow[tt][1] = (uint32_t)(32 * p + 16 * tt + 8 + g) * (AST * 2);
            }
#pragma unroll
            for (int pass = 0; pass < 3; pass++) {
                const char* Ap = smem + (pass == 2 ? OFF_A_LO : OFF_A_HI);
                const char* Bp = smem + (pass == 1 ? OFF_B_LO : OFF_B_HI);
#pragma unroll
                for (int s = 0; s < 4; s++) {
                    const uint32_t kbyte = (uint32_t)(s * 16 + c * 2) * 2;
                    uint32_t b0[8], b1[8];
#pragma unroll
                    for (int l = 0; l < 4; l++) {
                        const uint32_t brL = (uint32_t)((4 * j + l) * 8 + g) * (BST * 2);
                        b0[l] = *reinterpret_cast<const uint32_t*>(Bp + brL + kbyte);
                        b1[l] = *reinterpret_cast<const uint32_t*>(Bp + brL + kbyte + 16);
                        const uint32_t brV = (uint32_t)((8 + 4 * j + l) * 8 + g) * (BST * 2);
                        b0[4 + l] = *reinterpret_cast<const uint32_t*>(Bp + brV + kbyte);
                        b1[4 + l] = *reinterpret_cast<const uint32_t*>(Bp + brV + kbyte + 16);
                    }
#pragma unroll
                    for (int tt = 0; tt < 2; tt++) {
                        uint32_t a0 = *reinterpret_cast<const uint32_t*>(Ap + arow[tt][0] + kbyte);
                        uint32_t a1 = *reinterpret_cast<const uint32_t*>(Ap + arow[tt][1] + kbyte);
                        uint32_t a2 = *reinterpret_cast<const uint32_t*>(Ap + arow[tt][0] + kbyte + 16);
                        uint32_t a3 = *reinterpret_cast<const uint32_t*>(Ap + arow[tt][1] + kbyte + 16);
#pragma unroll
                        for (int nt = 0; nt < 8; nt++)
                            mma16816(acc[tt][nt], a0, a1, a2, a3, b0[nt], b1[nt]);
                    }
                }
            }
            // local softmax partials over this 32-col half; exp in place
#pragma unroll
            for (int tt = 0; tt < 2; tt++)
#pragma unroll
                for (int hh = 0; hh < 2; hh++) {
                    const int o = hh * 2;
                    float mx = -1e30f;
#pragma unroll
                    for (int l = 0; l < 4; l++)
                        mx = fmaxf(mx, fmaxf(acc[tt][l][o], acc[tt][l][o + 1]));
                    mx = fmaxf(mx, __shfl_xor_sync(0xffffffffu, mx, 1));
                    mx = fmaxf(mx, __shfl_xor_sync(0xffffffffu, mx, 2));
                    float s = 0.f;
#pragma unroll
                    for (int l = 0; l < 4; l++) {
                        acc[tt][l][o] = __expf(acc[tt][l][o] - mx);
                        acc[tt][l][o + 1] = __expf(acc[tt][l][o + 1] - mx);
                        s += acc[tt][l][o] + acc[tt][l][o + 1];
                    }
                    s += __shfl_xor_sync(0xffffffffu, s, 1);
                    s += __shfl_xor_sync(0xffffffffu, s, 2);
                    mxr[tt][hh] = mx; sr[tt][hh] = s;
                    if (c == 0) {
                        int rl = 16 * tt + 8 * hh + g;
                        exch[((p * 32 + rl) * 2 + j) * 2 + 0] = mx;
                        exch[((p * 32 + rl) * 2 + j) * 2 + 1] = s;
                    }
                }
        }
        __syncthreads();
        if (act) {
#pragma unroll
            for (int tt = 0; tt < 2; tt++)
#pragma unroll
                for (int hh = 0; hh < 2; hh++) {
                    const int o = hh * 2;
                    const int rl = 16 * tt + 8 * hh + g;
                    float hm2 = exch[((p * 32 + rl) * 2 + (1 - j)) * 2 + 0];
                    float s2 = exch[((p * 32 + rl) * 2 + (1 - j)) * 2 + 1];
                    float mx = mxr[tt][hh], s1 = sr[tt][hh];
                    float M = fmaxf(mx, hm2);
                    float e1 = __expf(mx - M), e2 = __expf(hm2 - M);
                    float scale = e1 * __fdividef(1.0f, s1 * e1 + s2 * e2);
                    const int r = 32 * p + rl;
                    if (r < 200) {
                        float* orow = outb + (size_t)r * 64;
#pragma unroll
                        for (int l = 0; l < 4; l++) {
                            int h = 32 * j + 8 * l + 2 * c;
                            float2 ov = make_float2(
                                acc[tt][4 + l][o] * acc[tt][l][o] * scale,
                                acc[tt][4 + l][o + 1] * acc[tt][l][o + 1] * scale);
                            *reinterpret_cast<float2*>(orow + h) = ov;
                        }
                    }
                }
        }
        __syncthreads();
    }
}

extern "C" void kernel_launch(void* const* d_in, const int* in_sizes, int n_in,
                              void* d_out, int out_size) {
    const float* q  = (const float*)d_in[0];
    const float* k  = (const float*)d_in[1];
    const float* Qw = (const float*)d_in[2];
    const float* Kw = (const float*)d_in[3];
    const float* Vw = (const float*)d_in[4];
    float* out = (float*)d_out;

    int B = in_sizes[0] / (200 * 64);  // 4096

    cudaFuncSetAttribute(fused_kernel, cudaFuncAttributeMaxDynamicSharedMemorySize, SMEM_TOTAL);

    prep_kernel<<<16, 256>>>(Qw, Kw);
    fused_kernel<<<B, 256, SMEM_TOTAL>>>(q, k, Vw, out);
}